// round 2
// baseline (speedup 1.0000x reference)
#include <cuda_runtime.h>
#include <math.h>

#define N_NODES 50000
#define N_EDGES 800000
#define E_TOT   850000           // edges + self loops
#define IN_F    256
#define OUT_F   128
#define LR_ALPHA 0.2f

#define SCAN_BLOCKS ((N_NODES + 255) / 256)   // 196

// ---- static device scratch (no runtime allocation allowed) ----
__device__ __align__(16) float g_Wh[(size_t)N_NODES * OUT_F];   // 25.6 MB
__device__ float g_ssrc[N_NODES];
__device__ float g_sdst[N_NODES];
__device__ int   g_cnt[N_NODES];
__device__ int   g_off[N_NODES + 1];
__device__ int   g_cur[N_NODES];
__device__ int   g_srow[E_TOT];
__device__ float g_se[E_TOT];
__device__ int   g_bsum[256];                     // SCAN_BLOCKS=196 used

// ===================================================================
// 1) GEMM: Wh = h @ W  (+ fused s_src = Wh.a1, s_dst = Wh.a2)
//    BM=64, BN=128(full), BK=32; 256 threads; 8x4 per-thread tile.
// ===================================================================
__global__ __launch_bounds__(256) void gemm_kernel(
    const float* __restrict__ h, const float* __restrict__ W,
    const float* __restrict__ a)
{
    __shared__ float As[32][65];    // [k][m], padded: conflict-free
    __shared__ float Bs[32][128];   // [k][n]

    const int tid = threadIdx.x;
    const int tx  = tid & 31;       // col group (lane)
    const int ty  = tid >> 5;       // row group (warp id)
    const int row0 = blockIdx.x * 64;

    float acc[8][4];
#pragma unroll
    for (int i = 0; i < 8; i++)
#pragma unroll
        for (int j = 0; j < 4; j++) acc[i][j] = 0.0f;

    for (int k0 = 0; k0 < IN_F; k0 += 32) {
        // load A tile: 64 rows x 32 k  (512 float4, 2 per thread)
#pragma unroll
        for (int p = 0; p < 2; p++) {
            int q  = tid + p * 256;
            int r  = q >> 3;            // 0..63
            int kq = (q & 7) * 4;       // 0,4,...,28
            int grow = row0 + r;
            float4 v = make_float4(0.f, 0.f, 0.f, 0.f);
            if (grow < N_NODES)
                v = *(const float4*)(h + (size_t)grow * IN_F + k0 + kq);
            As[kq + 0][r] = v.x;
            As[kq + 1][r] = v.y;
            As[kq + 2][r] = v.z;
            As[kq + 3][r] = v.w;
        }
        // load B tile: 32 k x 128 n (1024 float4, 4 per thread)
#pragma unroll
        for (int p = 0; p < 4; p++) {
            int kk = ty + p * 8;        // 0..31
            float4 v = *(const float4*)(W + (size_t)(k0 + kk) * OUT_F + tx * 4);
            *(float4*)&Bs[kk][tx * 4] = v;
        }
        __syncthreads();

#pragma unroll
        for (int k = 0; k < 32; k++) {
            float4 b = *(float4*)&Bs[k][tx * 4];
#pragma unroll
            for (int i = 0; i < 8; i++) {
                float av = As[k][ty * 8 + i];   // broadcast within warp
                acc[i][0] += av * b.x;
                acc[i][1] += av * b.y;
                acc[i][2] += av * b.z;
                acc[i][3] += av * b.w;
            }
        }
        __syncthreads();
    }

    // epilogue: store Wh + fused attention-vector dots
    float a1x = a[tx * 4 + 0], a1y = a[tx * 4 + 1];
    float a1z = a[tx * 4 + 2], a1w = a[tx * 4 + 3];
    float a2x = a[OUT_F + tx * 4 + 0], a2y = a[OUT_F + tx * 4 + 1];
    float a2z = a[OUT_F + tx * 4 + 2], a2w = a[OUT_F + tx * 4 + 3];

#pragma unroll
    for (int i = 0; i < 8; i++) {
        int grow = row0 + ty * 8 + i;
        float s1 = acc[i][0] * a1x + acc[i][1] * a1y + acc[i][2] * a1z + acc[i][3] * a1w;
        float s2 = acc[i][0] * a2x + acc[i][1] * a2y + acc[i][2] * a2z + acc[i][3] * a2w;
#pragma unroll
        for (int o = 16; o; o >>= 1) {
            s1 += __shfl_xor_sync(0xffffffffu, s1, o);
            s2 += __shfl_xor_sync(0xffffffffu, s2, o);
        }
        if (grow < N_NODES) {
            *(float4*)(g_Wh + (size_t)grow * OUT_F + tx * 4) =
                make_float4(acc[i][0], acc[i][1], acc[i][2], acc[i][3]);
            if (tx == 0) { g_ssrc[grow] = s1; g_sdst[grow] = s2; }
        }
    }
}

// ===================================================================
// 2) counting sort of edges by destination  (adj is INT32: [2, E] row-major)
// ===================================================================
__global__ void zero_cnt_kernel()
{
    int i = blockIdx.x * blockDim.x + threadIdx.x;
    if (i < N_NODES) g_cnt[i] = 0;
}

__global__ void hist_kernel(const int* __restrict__ adj)
{
    int i = blockIdx.x * blockDim.x + threadIdx.x;
    if (i >= E_TOT) return;
    int c = (i < N_EDGES) ? adj[N_EDGES + i] : (i - N_EDGES);
    atomicAdd(&g_cnt[c], 1);
}

__device__ __forceinline__ int block_scan_256(int v, int* wsum)
{
    int tid = threadIdx.x, lane = tid & 31, w = tid >> 5;
    int x = v;
#pragma unroll
    for (int o = 1; o < 32; o <<= 1) {
        int t = __shfl_up_sync(0xffffffffu, x, o);
        if (lane >= o) x += t;
    }
    if (lane == 31) wsum[w] = x;
    __syncthreads();
    if (w == 0) {
        int y = (lane < 8) ? wsum[lane] : 0;
#pragma unroll
        for (int o = 1; o < 8; o <<= 1) {
            int t = __shfl_up_sync(0xffffffffu, y, o);
            if (lane >= o) y += t;
        }
        if (lane < 8) wsum[lane] = y;
    }
    __syncthreads();
    if (w > 0) x += wsum[w - 1];
    return x;   // inclusive scan of the 256 block values
}

__global__ void scan_block_kernel()
{
    __shared__ int wsum[8];
    int i = blockIdx.x * 256 + threadIdx.x;
    int v = (i < N_NODES) ? g_cnt[i] : 0;
    int x = block_scan_256(v, wsum);
    if (i < N_NODES) g_off[i] = x - v;          // block-local exclusive
    if (threadIdx.x == 255) g_bsum[blockIdx.x] = x;
}

__global__ void scan_top_kernel()
{
    __shared__ int wsum[8];
    int i = threadIdx.x;
    int v = (i < SCAN_BLOCKS) ? g_bsum[i] : 0;
    int x = block_scan_256(v, wsum);
    g_bsum[i] = x - v;                          // exclusive block bases
}

__global__ void scan_add_kernel()
{
    int i = blockIdx.x * blockDim.x + threadIdx.x;
    if (i < N_NODES) {
        int o = g_off[i] + g_bsum[i >> 8];
        g_off[i] = o;
        g_cur[i] = o;
    }
    if (i == 0) g_off[N_NODES] = E_TOT;
}

__global__ void sort_scatter_kernel(const int* __restrict__ adj)
{
    int i = blockIdx.x * blockDim.x + threadIdx.x;
    if (i >= E_TOT) return;
    int r, c;
    if (i < N_EDGES) { r = adj[i]; c = adj[N_EDGES + i]; }
    else             { r = i - N_EDGES; c = r; }
    int pos = atomicAdd(&g_cur[c], 1);
    g_srow[pos] = r;
    float e = g_sdst[c] + g_ssrc[r];
    g_se[pos] = (e > 0.f) ? e : LR_ALPHA * e;   // leaky relu
}

// ===================================================================
// 3) per-destination segment softmax + weighted sum + ELU
//    One warp per destination node. No fp atomics.
// ===================================================================
__global__ __launch_bounds__(256) void aggregate_kernel(float* __restrict__ out)
{
    int gw   = (blockIdx.x * blockDim.x + threadIdx.x) >> 5;
    int lane = threadIdx.x & 31;
    if (gw >= N_NODES) return;

    int beg = g_off[gw];
    int end = g_off[gw + 1];

    // pass 1: segment max
    float m = -3.0e38f;
    for (int k = beg + lane; k < end; k += 32) m = fmaxf(m, g_se[k]);
#pragma unroll
    for (int o = 16; o; o >>= 1) m = fmaxf(m, __shfl_xor_sync(0xffffffffu, m, o));

    // pass 2: denom
    float s = 0.f;
    for (int k = beg + lane; k < end; k += 32) s += __expf(g_se[k] - m);
#pragma unroll
    for (int o = 16; o; o >>= 1) s += __shfl_xor_sync(0xffffffffu, s, o);
    float inv = 1.0f / s;

    // pass 3: weighted feature accumulation (lane owns 4 features)
    float4 acc = make_float4(0.f, 0.f, 0.f, 0.f);
    for (int k0 = beg; k0 < end; k0 += 32) {
        int kk = k0 + lane;
        int   r   = 0;
        float att = 0.f;
        if (kk < end) {
            r   = g_srow[kk];
            att = __expf(g_se[kk] - m) * inv;
        }
        int cnt = min(32, end - k0);
        for (int j = 0; j < cnt; j++) {
            float aj = __shfl_sync(0xffffffffu, att, j);
            int   rj = __shfl_sync(0xffffffffu, r, j);
            float4 w = *(const float4*)(g_Wh + (size_t)rj * OUT_F + lane * 4);
            acc.x += aj * w.x;
            acc.y += aj * w.y;
            acc.z += aj * w.z;
            acc.w += aj * w.w;
        }
    }

    // fused ELU
    acc.x = (acc.x > 0.f) ? acc.x : (__expf(acc.x) - 1.f);
    acc.y = (acc.y > 0.f) ? acc.y : (__expf(acc.y) - 1.f);
    acc.z = (acc.z > 0.f) ? acc.z : (__expf(acc.z) - 1.f);
    acc.w = (acc.w > 0.f) ? acc.w : (__expf(acc.w) - 1.f);

    *(float4*)(out + (size_t)gw * OUT_F + lane * 4) = acc;
}

// ===================================================================
extern "C" void kernel_launch(void* const* d_in, const int* in_sizes, int n_in,
                              void* d_out, int out_size)
{
    (void)in_sizes; (void)n_in; (void)out_size;
    const float* h   = (const float*)d_in[0];
    const int*   adj = (const int*)d_in[1];
    const float* W   = (const float*)d_in[2];
    const float* a   = (const float*)d_in[3];
    float*       out = (float*)d_out;

    const int EB = (E_TOT + 255) / 256;

    zero_cnt_kernel<<<SCAN_BLOCKS, 256>>>();
    gemm_kernel<<<(N_NODES + 63) / 64, 256>>>(h, W, a);
    hist_kernel<<<EB, 256>>>(adj);
    scan_block_kernel<<<SCAN_BLOCKS, 256>>>();
    scan_top_kernel<<<1, 256>>>();
    scan_add_kernel<<<SCAN_BLOCKS, 256>>>();
    sort_scatter_kernel<<<EB, 256>>>(adj);
    aggregate_kernel<<<(N_NODES * 32 + 255) / 256, 256>>>(out);
}

// round 4
// speedup vs baseline: 1.3943x; 1.3943x over previous
#include <cuda_runtime.h>
#include <cstdint>
#include <math.h>

#define N_NODES 50000
#define N_EDGES 800000
#define E_TOT   850000
#define IN_F    256
#define OUT_F   128
#define LR_ALPHA 0.2f

#define SCAN_BLOCKS ((N_NODES + 255) / 256)   // 196
#define GEMM_CTAS   ((N_NODES + 127) / 128)   // 391
#define N_CHUNKS    (IN_F / 32)               // 8
#define AS_STRIDE   36

// ---- static device scratch ----
__device__ __align__(16) float g_Wh[(size_t)N_NODES * OUT_F];   // 25.6 MB
__device__ __align__(16) float g_WT[(size_t)OUT_F * IN_F];      // W^T [n][k]
__device__ float g_ssrc[N_NODES];
__device__ float g_sdst[N_NODES];
__device__ int   g_cnt[N_NODES];
__device__ int   g_off[N_NODES + 1];
__device__ int   g_cur[N_NODES];
__device__ int   g_srow[E_TOT];
__device__ float g_se[E_TOT];
__device__ int   g_bsum[256];

__device__ __forceinline__ uint32_t f2tf32(float x) {
    uint32_t r;
    asm("cvt.rna.tf32.f32 %0, %1;" : "=r"(r) : "f"(x));
    return r;
}

__device__ __forceinline__ void mma_tf32(float* d, const uint32_t* af,
                                         uint32_t b0, uint32_t b1) {
    asm volatile(
        "mma.sync.aligned.m16n8k8.row.col.f32.tf32.tf32.f32 "
        "{%0,%1,%2,%3}, {%4,%5,%6,%7}, {%8,%9}, {%0,%1,%2,%3};"
        : "+f"(d[0]), "+f"(d[1]), "+f"(d[2]), "+f"(d[3])
        : "r"(af[0]), "r"(af[1]), "r"(af[2]), "r"(af[3]), "r"(b0), "r"(b1));
}

// =============== W transpose: g_WT[n][k] = W[k][n] ===============
__global__ void transpose_W_kernel(const float* __restrict__ W)
{
    int i = blockIdx.x * 256 + threadIdx.x;
    if (i < IN_F * OUT_F) {
        int k = i >> 7, n = i & 127;
        g_WT[(size_t)n * IN_F + k] = W[i];
    }
}

// =============== mma.sync tf32 GEMM: Wh = h @ W ===============
// CTA: 128x128; 8 warps 2(M)x4(N); warp tile 64x32; BK=32, 8 chunks.
__global__ __launch_bounds__(256) void gemm_mma_kernel(const float* __restrict__ h)
{
    __shared__ float As[128 * AS_STRIDE];   // [m][k], stride 36 (conflict-free frags)
    __shared__ float Bs[128 * AS_STRIDE];   // [n][k], stride 36

    const int tid    = threadIdx.x;
    const int wid    = tid >> 5;
    const int lane   = tid & 31;
    const int warp_m = wid & 1;        // 0..1  -> 64 rows each
    const int warp_n = wid >> 1;       // 0..3  -> 32 cols each
    const int row0   = blockIdx.x * 128;

    float acc[4][4][4];
#pragma unroll
    for (int mt = 0; mt < 4; mt++)
#pragma unroll
        for (int nt = 0; nt < 4; nt++)
#pragma unroll
            for (int j = 0; j < 4; j++) acc[mt][nt][j] = 0.0f;

    float4 pa[4], pb[4];
    // prefetch chunk 0
#pragma unroll
    for (int p = 0; p < 4; p++) {
        int idx = tid + p * 256;           // 0..1023
        int r   = idx >> 3;                // 0..127
        int kq  = (idx & 7) << 2;          // 0,4..28
        int grow = row0 + r;
        pa[p] = make_float4(0.f, 0.f, 0.f, 0.f);
        if (grow < N_NODES)
            pa[p] = *(const float4*)(h + (size_t)grow * IN_F + kq);
        pb[p] = *(const float4*)(g_WT + (size_t)r * IN_F + kq);
    }

    for (int c = 0; c < N_CHUNKS; c++) {
        // store prefetched chunk to smem (with tf32 rounding)
#pragma unroll
        for (int p = 0; p < 4; p++) {
            int idx = tid + p * 256;
            int r   = idx >> 3;
            int kq  = (idx & 7) << 2;
            float* da = As + r * AS_STRIDE + kq;
            da[0] = __uint_as_float(f2tf32(pa[p].x));
            da[1] = __uint_as_float(f2tf32(pa[p].y));
            da[2] = __uint_as_float(f2tf32(pa[p].z));
            da[3] = __uint_as_float(f2tf32(pa[p].w));
            float* db = Bs + r * AS_STRIDE + kq;
            db[0] = __uint_as_float(f2tf32(pb[p].x));
            db[1] = __uint_as_float(f2tf32(pb[p].y));
            db[2] = __uint_as_float(f2tf32(pb[p].z));
            db[3] = __uint_as_float(f2tf32(pb[p].w));
        }
        __syncthreads();

        // prefetch next chunk
        if (c + 1 < N_CHUNKS) {
            int ko = (c + 1) * 32;
#pragma unroll
            for (int p = 0; p < 4; p++) {
                int idx = tid + p * 256;
                int r   = idx >> 3;
                int kq  = (idx & 7) << 2;
                int grow = row0 + r;
                pa[p] = make_float4(0.f, 0.f, 0.f, 0.f);
                if (grow < N_NODES)
                    pa[p] = *(const float4*)(h + (size_t)grow * IN_F + ko + kq);
                pb[p] = *(const float4*)(g_WT + (size_t)r * IN_F + ko + kq);
            }
        }

        // compute: 4 k-steps of 8
#pragma unroll
        for (int ks = 0; ks < 4; ks++) {
            uint32_t af[4][4];
#pragma unroll
            for (int mt = 0; mt < 4; mt++) {
                int ar = warp_m * 64 + mt * 16 + (lane >> 2);
                int ac = ks * 8 + (lane & 3);
                af[mt][0] = __float_as_uint(As[ar * AS_STRIDE + ac]);
                af[mt][1] = __float_as_uint(As[(ar + 8) * AS_STRIDE + ac]);
                af[mt][2] = __float_as_uint(As[ar * AS_STRIDE + ac + 4]);
                af[mt][3] = __float_as_uint(As[(ar + 8) * AS_STRIDE + ac + 4]);
            }
#pragma unroll
            for (int nt = 0; nt < 4; nt++) {
                int bn = warp_n * 32 + nt * 8 + (lane >> 2);
                int bk = ks * 8 + (lane & 3);
                uint32_t b0 = __float_as_uint(Bs[bn * AS_STRIDE + bk]);
                uint32_t b1 = __float_as_uint(Bs[bn * AS_STRIDE + bk + 4]);
#pragma unroll
                for (int mt = 0; mt < 4; mt++)
                    mma_tf32(acc[mt][nt], af[mt], b0, b1);
            }
        }
        __syncthreads();
    }

    // epilogue: write Wh. D frag: c0/c1 -> row lane>>2, cols 2q,2q+1; c2/c3 -> row+8.
#pragma unroll
    for (int mt = 0; mt < 4; mt++) {
#pragma unroll
        for (int r2 = 0; r2 < 2; r2++) {
            int row = row0 + warp_m * 64 + mt * 16 + (lane >> 2) + r2 * 8;
            if (row < N_NODES) {
                float* dst = g_Wh + (size_t)row * OUT_F + warp_n * 32 + (lane & 3) * 2;
#pragma unroll
                for (int nt = 0; nt < 4; nt++)
                    *(float2*)(dst + nt * 8) =
                        make_float2(acc[mt][nt][r2 * 2], acc[mt][nt][r2 * 2 + 1]);
            }
        }
    }
}

// =============== s_src/s_dst = Wh . a1 / a2  (one warp per node) ===============
__global__ __launch_bounds__(256) void sdots_kernel(const float* __restrict__ a)
{
    int gw   = (blockIdx.x * blockDim.x + threadIdx.x) >> 5;
    int lane = threadIdx.x & 31;
    if (gw >= N_NODES) return;
    float4 w  = *(const float4*)(g_Wh + (size_t)gw * OUT_F + lane * 4);
    float4 a1 = *(const float4*)(a + lane * 4);
    float4 a2 = *(const float4*)(a + OUT_F + lane * 4);
    float s1 = w.x * a1.x + w.y * a1.y + w.z * a1.z + w.w * a1.w;
    float s2 = w.x * a2.x + w.y * a2.y + w.z * a2.z + w.w * a2.w;
#pragma unroll
    for (int o = 16; o; o >>= 1) {
        s1 += __shfl_xor_sync(0xffffffffu, s1, o);
        s2 += __shfl_xor_sync(0xffffffffu, s2, o);
    }
    if (lane == 0) { g_ssrc[gw] = s1; g_sdst[gw] = s2; }
}

// =============== counting sort of edges by destination (adj int32 [2,E]) ===============
__global__ void zero_cnt_kernel()
{
    int i = blockIdx.x * blockDim.x + threadIdx.x;
    if (i < N_NODES) g_cnt[i] = 0;
}

__global__ void hist_kernel(const int* __restrict__ adj)
{
    int i = blockIdx.x * blockDim.x + threadIdx.x;
    if (i >= E_TOT) return;
    int c = (i < N_EDGES) ? adj[N_EDGES + i] : (i - N_EDGES);
    atomicAdd(&g_cnt[c], 1);
}

__device__ __forceinline__ int block_scan_256(int v, int* wsum)
{
    int tid = threadIdx.x, lane = tid & 31, w = tid >> 5;
    int x = v;
#pragma unroll
    for (int o = 1; o < 32; o <<= 1) {
        int t = __shfl_up_sync(0xffffffffu, x, o);
        if (lane >= o) x += t;
    }
    if (lane == 31) wsum[w] = x;
    __syncthreads();
    if (w == 0) {
        int y = (lane < 8) ? wsum[lane] : 0;
#pragma unroll
        for (int o = 1; o < 8; o <<= 1) {
            int t = __shfl_up_sync(0xffffffffu, y, o);
            if (lane >= o) y += t;
        }
        if (lane < 8) wsum[lane] = y;
    }
    __syncthreads();
    if (w > 0) x += wsum[w - 1];
    return x;
}

__global__ void scan_block_kernel()
{
    __shared__ int wsum[8];
    int i = blockIdx.x * 256 + threadIdx.x;
    int v = (i < N_NODES) ? g_cnt[i] : 0;
    int x = block_scan_256(v, wsum);
    if (i < N_NODES) g_off[i] = x - v;
    if (threadIdx.x == 255) g_bsum[blockIdx.x] = x;
}

__global__ void scan_top_kernel()
{
    __shared__ int wsum[8];
    int i = threadIdx.x;
    int v = (i < SCAN_BLOCKS) ? g_bsum[i] : 0;
    int x = block_scan_256(v, wsum);
    g_bsum[i] = x - v;
}

__global__ void scan_add_kernel()
{
    int i = blockIdx.x * blockDim.x + threadIdx.x;
    if (i < N_NODES) {
        int o = g_off[i] + g_bsum[i >> 8];
        g_off[i] = o;
        g_cur[i] = o;
    }
    if (i == 0) g_off[N_NODES] = E_TOT;
}

__global__ void sort_scatter_kernel(const int* __restrict__ adj)
{
    int i = blockIdx.x * blockDim.x + threadIdx.x;
    if (i >= E_TOT) return;
    int r, c;
    if (i < N_EDGES) { r = adj[i]; c = adj[N_EDGES + i]; }
    else             { r = i - N_EDGES; c = r; }
    int pos = atomicAdd(&g_cur[c], 1);
    g_srow[pos] = r;
    float e = g_sdst[c] + g_ssrc[r];
    g_se[pos] = (e > 0.f) ? e : LR_ALPHA * e;
}

// =============== per-destination softmax + weighted sum + ELU ===============
__global__ __launch_bounds__(256) void aggregate_kernel(float* __restrict__ out)
{
    int gw   = (blockIdx.x * blockDim.x + threadIdx.x) >> 5;
    int lane = threadIdx.x & 31;
    if (gw >= N_NODES) return;

    int beg = g_off[gw];
    int end = g_off[gw + 1];

    float m = -3.0e38f;
    for (int k = beg + lane; k < end; k += 32) m = fmaxf(m, g_se[k]);
#pragma unroll
    for (int o = 16; o; o >>= 1) m = fmaxf(m, __shfl_xor_sync(0xffffffffu, m, o));

    float s = 0.f;
    for (int k = beg + lane; k < end; k += 32) s += __expf(g_se[k] - m);
#pragma unroll
    for (int o = 16; o; o >>= 1) s += __shfl_xor_sync(0xffffffffu, s, o);
    float inv = 1.0f / s;

    float4 acc = make_float4(0.f, 0.f, 0.f, 0.f);
    for (int k0 = beg; k0 < end; k0 += 32) {
        int kk = k0 + lane;
        int   r   = 0;
        float att = 0.f;
        if (kk < end) {
            r   = g_srow[kk];
            att = __expf(g_se[kk] - m) * inv;
        }
        int cnt = min(32, end - k0);
        for (int j = 0; j < cnt; j++) {
            float aj = __shfl_sync(0xffffffffu, att, j);
            int   rj = __shfl_sync(0xffffffffu, r, j);
            float4 w = *(const float4*)(g_Wh + (size_t)rj * OUT_F + lane * 4);
            acc.x += aj * w.x;
            acc.y += aj * w.y;
            acc.z += aj * w.z;
            acc.w += aj * w.w;
        }
    }

    acc.x = (acc.x > 0.f) ? acc.x : (__expf(acc.x) - 1.f);
    acc.y = (acc.y > 0.f) ? acc.y : (__expf(acc.y) - 1.f);
    acc.z = (acc.z > 0.f) ? acc.z : (__expf(acc.z) - 1.f);
    acc.w = (acc.w > 0.f) ? acc.w : (__expf(acc.w) - 1.f);

    *(float4*)(out + (size_t)gw * OUT_F + lane * 4) = acc;
}

// ===================================================================
extern "C" void kernel_launch(void* const* d_in, const int* in_sizes, int n_in,
                              void* d_out, int out_size)
{
    (void)in_sizes; (void)n_in; (void)out_size;
    const float* h   = (const float*)d_in[0];
    const int*   adj = (const int*)d_in[1];
    const float* W   = (const float*)d_in[2];
    const float* a   = (const float*)d_in[3];
    float*       out = (float*)d_out;

    const int EB = (E_TOT + 255) / 256;
    const int WB = (N_NODES * 32 + 255) / 256;

    zero_cnt_kernel<<<SCAN_BLOCKS, 256>>>();
    transpose_W_kernel<<<(IN_F * OUT_F + 255) / 256, 256>>>(W);
    gemm_mma_kernel<<<GEMM_CTAS, 256>>>(h);
    sdots_kernel<<<WB, 256>>>(a);
    hist_kernel<<<EB, 256>>>(adj);
    scan_block_kernel<<<SCAN_BLOCKS, 256>>>();
    scan_top_kernel<<<1, 256>>>();
    scan_add_kernel<<<SCAN_BLOCKS, 256>>>();
    sort_scatter_kernel<<<EB, 256>>>(adj);
    aggregate_kernel<<<WB, 256>>>(out);
}

// round 5
// speedup vs baseline: 1.4705x; 1.0546x over previous
#include <cuda_runtime.h>
#include <cstdint>
#include <math.h>

#define N_NODES 50000
#define N_EDGES 800000
#define E_TOT   850000
#define IN_F    256
#define OUT_F   128
#define LR_ALPHA 0.2f

#define SCAN_BLOCKS ((N_NODES + 255) / 256)   // 196
#define GEMM_CTAS   ((N_NODES + 127) / 128)   // 391
#define N_CHUNKS    (IN_F / 32)               // 8
#define AS_STRIDE   36

// ---- static device scratch ----
__device__ __align__(16) float g_Wh[(size_t)N_NODES * OUT_F];   // 25.6 MB
__device__ __align__(16) float g_WT[(size_t)OUT_F * IN_F];      // W^T [n][k]
__device__ float g_ssrc[N_NODES];
__device__ float g_sdst[N_NODES];
__device__ int   g_cnt[N_NODES];
__device__ int   g_off[N_NODES + 1];
__device__ int   g_cur[N_NODES];
__device__ int   g_srow[E_TOT];
__device__ float g_se[E_TOT];
__device__ int   g_bsum[256];

__device__ __forceinline__ uint32_t f2tf32(float x) {
    uint32_t r;
    asm("cvt.rna.tf32.f32 %0, %1;" : "=r"(r) : "f"(x));
    return r;
}

__device__ __forceinline__ void mma_tf32(float* d, const uint32_t* af,
                                         uint32_t b0, uint32_t b1) {
    asm volatile(
        "mma.sync.aligned.m16n8k8.row.col.f32.tf32.tf32.f32 "
        "{%0,%1,%2,%3}, {%4,%5,%6,%7}, {%8,%9}, {%0,%1,%2,%3};"
        : "+f"(d[0]), "+f"(d[1]), "+f"(d[2]), "+f"(d[3])
        : "r"(af[0]), "r"(af[1]), "r"(af[2]), "r"(af[3]), "r"(b0), "r"(b1));
}

// =============== W transpose + counter zeroing (fused, one launch) ===============
__global__ void prep_kernel(const float* __restrict__ W)
{
    int i = blockIdx.x * 256 + threadIdx.x;
    if (i < IN_F * OUT_F) {
        int k = i >> 7, n = i & 127;
        g_WT[(size_t)n * IN_F + k] = W[i];
    }
    if (i < N_NODES) g_cnt[i] = 0;
}

// =============== mma.sync tf32 GEMM: Wh = h @ W (+ fused s_src/s_dst) ===============
// CTA: 128x128; 8 warps 2(M)x4(N); warp tile 64x32; BK=32, 8 chunks.
__global__ __launch_bounds__(256) void gemm_mma_kernel(
    const float* __restrict__ h, const float* __restrict__ a)
{
    __shared__ float As[128 * AS_STRIDE];   // [m][k], stride 36 (conflict-free frags)
    __shared__ float Bs[128 * AS_STRIDE];   // [n][k], stride 36

    const int tid    = threadIdx.x;
    const int wid    = tid >> 5;
    const int lane   = tid & 31;
    const int warp_m = wid & 1;        // 0..1  -> 64 rows each
    const int warp_n = wid >> 1;       // 0..3  -> 32 cols each
    const int row0   = blockIdx.x * 128;

    float acc[4][4][4];
#pragma unroll
    for (int mt = 0; mt < 4; mt++)
#pragma unroll
        for (int nt = 0; nt < 4; nt++)
#pragma unroll
            for (int j = 0; j < 4; j++) acc[mt][nt][j] = 0.0f;

    float4 pa[4], pb[4];
    // prefetch chunk 0
#pragma unroll
    for (int p = 0; p < 4; p++) {
        int idx = tid + p * 256;           // 0..1023
        int r   = idx >> 3;                // 0..127
        int kq  = (idx & 7) << 2;          // 0,4..28
        int grow = row0 + r;
        pa[p] = make_float4(0.f, 0.f, 0.f, 0.f);
        if (grow < N_NODES)
            pa[p] = *(const float4*)(h + (size_t)grow * IN_F + kq);
        pb[p] = *(const float4*)(g_WT + (size_t)r * IN_F + kq);
    }

    for (int c = 0; c < N_CHUNKS; c++) {
        // store prefetched chunk to smem (with tf32 rounding)
#pragma unroll
        for (int p = 0; p < 4; p++) {
            int idx = tid + p * 256;
            int r   = idx >> 3;
            int kq  = (idx & 7) << 2;
            float* da = As + r * AS_STRIDE + kq;
            da[0] = __uint_as_float(f2tf32(pa[p].x));
            da[1] = __uint_as_float(f2tf32(pa[p].y));
            da[2] = __uint_as_float(f2tf32(pa[p].z));
            da[3] = __uint_as_float(f2tf32(pa[p].w));
            float* db = Bs + r * AS_STRIDE + kq;
            db[0] = __uint_as_float(f2tf32(pb[p].x));
            db[1] = __uint_as_float(f2tf32(pb[p].y));
            db[2] = __uint_as_float(f2tf32(pb[p].z));
            db[3] = __uint_as_float(f2tf32(pb[p].w));
        }
        __syncthreads();

        // prefetch next chunk
        if (c + 1 < N_CHUNKS) {
            int ko = (c + 1) * 32;
#pragma unroll
            for (int p = 0; p < 4; p++) {
                int idx = tid + p * 256;
                int r   = idx >> 3;
                int kq  = (idx & 7) << 2;
                int grow = row0 + r;
                pa[p] = make_float4(0.f, 0.f, 0.f, 0.f);
                if (grow < N_NODES)
                    pa[p] = *(const float4*)(h + (size_t)grow * IN_F + ko + kq);
                pb[p] = *(const float4*)(g_WT + (size_t)r * IN_F + ko + kq);
            }
        }

        // compute: 4 k-steps of 8
#pragma unroll
        for (int ks = 0; ks < 4; ks++) {
            uint32_t af[4][4];
#pragma unroll
            for (int mt = 0; mt < 4; mt++) {
                int ar = warp_m * 64 + mt * 16 + (lane >> 2);
                int ac = ks * 8 + (lane & 3);
                af[mt][0] = __float_as_uint(As[ar * AS_STRIDE + ac]);
                af[mt][1] = __float_as_uint(As[(ar + 8) * AS_STRIDE + ac]);
                af[mt][2] = __float_as_uint(As[ar * AS_STRIDE + ac + 4]);
                af[mt][3] = __float_as_uint(As[(ar + 8) * AS_STRIDE + ac + 4]);
            }
#pragma unroll
            for (int nt = 0; nt < 4; nt++) {
                int bn = warp_n * 32 + nt * 8 + (lane >> 2);
                int bk = ks * 8 + (lane & 3);
                uint32_t b0 = __float_as_uint(Bs[bn * AS_STRIDE + bk]);
                uint32_t b1 = __float_as_uint(Bs[bn * AS_STRIDE + bk + 4]);
#pragma unroll
                for (int mt = 0; mt < 4; mt++)
                    mma_tf32(acc[mt][nt], af[mt], b0, b1);
            }
        }
        __syncthreads();
    }

    // ---- epilogue: write Wh + fused s_src/s_dst dots ----
    // D frag: c0/c1 -> row lane>>2, cols (lane&3)*2,+1; c2/c3 -> row+8.
    // Thread's 8 cols: warp_n*32 + nt*8 + (lane&3)*2 + {0,1}
    float a1v[8], a2v[8];
#pragma unroll
    for (int nt = 0; nt < 4; nt++) {
        int cc = warp_n * 32 + nt * 8 + (lane & 3) * 2;
        a1v[nt * 2]     = a[cc];
        a1v[nt * 2 + 1] = a[cc + 1];
        a2v[nt * 2]     = a[OUT_F + cc];
        a2v[nt * 2 + 1] = a[OUT_F + cc + 1];
    }

    float* red = As;   // reuse: [4 warp_n][128 rows] s1, then s2 (1024 floats)

#pragma unroll
    for (int mt = 0; mt < 4; mt++) {
#pragma unroll
        for (int r2 = 0; r2 < 2; r2++) {
            int rt  = warp_m * 64 + mt * 16 + (lane >> 2) + r2 * 8;  // row in tile
            int row = row0 + rt;
            float s1 = 0.f, s2 = 0.f;
#pragma unroll
            for (int nt = 0; nt < 4; nt++) {
                float v0 = acc[mt][nt][r2 * 2];
                float v1 = acc[mt][nt][r2 * 2 + 1];
                s1 += v0 * a1v[nt * 2] + v1 * a1v[nt * 2 + 1];
                s2 += v0 * a2v[nt * 2] + v1 * a2v[nt * 2 + 1];
            }
            // reduce across the 4 lanes sharing this row (lane&3 = 0..3)
            s1 += __shfl_xor_sync(0xffffffffu, s1, 1);
            s1 += __shfl_xor_sync(0xffffffffu, s1, 2);
            s2 += __shfl_xor_sync(0xffffffffu, s2, 1);
            s2 += __shfl_xor_sync(0xffffffffu, s2, 2);
            if ((lane & 3) == 0) {
                red[warp_n * 128 + rt]       = s1;
                red[512 + warp_n * 128 + rt] = s2;
            }
            if (row < N_NODES) {
                float* dst = g_Wh + (size_t)row * OUT_F + warp_n * 32 + (lane & 3) * 2;
#pragma unroll
                for (int nt = 0; nt < 4; nt++)
                    *(float2*)(dst + nt * 8) =
                        make_float2(acc[mt][nt][r2 * 2], acc[mt][nt][r2 * 2 + 1]);
            }
        }
    }
    __syncthreads();
    {
        int rt  = tid & 127;
        int row = row0 + rt;
        if (row < N_NODES) {
            if (tid < 128)
                g_ssrc[row] = red[rt] + red[128 + rt] + red[256 + rt] + red[384 + rt];
            else
                g_sdst[row] = red[512 + rt] + red[640 + rt] + red[768 + rt] + red[896 + rt];
        }
    }
}

// =============== counting sort of edges by destination (adj int32 [2,E]) ===============
__global__ void hist_kernel(const int* __restrict__ adj)
{
    int i = blockIdx.x * blockDim.x + threadIdx.x;
    if (i >= E_TOT) return;
    int c = (i < N_EDGES) ? adj[N_EDGES + i] : (i - N_EDGES);
    atomicAdd(&g_cnt[c], 1);
}

__device__ __forceinline__ int block_scan_256(int v, int* wsum)
{
    int tid = threadIdx.x, lane = tid & 31, w = tid >> 5;
    int x = v;
#pragma unroll
    for (int o = 1; o < 32; o <<= 1) {
        int t = __shfl_up_sync(0xffffffffu, x, o);
        if (lane >= o) x += t;
    }
    if (lane == 31) wsum[w] = x;
    __syncthreads();
    if (w == 0) {
        int y = (lane < 8) ? wsum[lane] : 0;
#pragma unroll
        for (int o = 1; o < 8; o <<= 1) {
            int t = __shfl_up_sync(0xffffffffu, y, o);
            if (lane >= o) y += t;
        }
        if (lane < 8) wsum[lane] = y;
    }
    __syncthreads();
    if (w > 0) x += wsum[w - 1];
    return x;
}

__global__ void scan_block_kernel()
{
    __shared__ int wsum[8];
    int i = blockIdx.x * 256 + threadIdx.x;
    int v = (i < N_NODES) ? g_cnt[i] : 0;
    int x = block_scan_256(v, wsum);
    if (i < N_NODES) g_off[i] = x - v;
    if (threadIdx.x == 255) g_bsum[blockIdx.x] = x;
}

__global__ void scan_top_kernel()
{
    __shared__ int wsum[8];
    int i = threadIdx.x;
    int v = (i < SCAN_BLOCKS) ? g_bsum[i] : 0;
    int x = block_scan_256(v, wsum);
    g_bsum[i] = x - v;
}

__global__ void scan_add_kernel()
{
    int i = blockIdx.x * blockDim.x + threadIdx.x;
    if (i < N_NODES) {
        int o = g_off[i] + g_bsum[i >> 8];
        g_off[i] = o;
        g_cur[i] = o;
    }
    if (i == 0) g_off[N_NODES] = E_TOT;
}

__global__ void sort_scatter_kernel(const int* __restrict__ adj)
{
    int i = blockIdx.x * blockDim.x + threadIdx.x;
    if (i >= E_TOT) return;
    int r, c;
    if (i < N_EDGES) { r = adj[i]; c = adj[N_EDGES + i]; }
    else             { r = i - N_EDGES; c = r; }
    int pos = atomicAdd(&g_cur[c], 1);
    g_srow[pos] = r;
    float e = g_sdst[c] + g_ssrc[r];
    g_se[pos] = (e > 0.f) ? e : LR_ALPHA * e;
}

// =============== per-destination softmax + weighted sum + ELU ===============
__global__ __launch_bounds__(256) void aggregate_kernel(float* __restrict__ out)
{
    int gw   = (blockIdx.x * blockDim.x + threadIdx.x) >> 5;
    int lane = threadIdx.x & 31;
    if (gw >= N_NODES) return;

    int beg = g_off[gw];
    int end = g_off[gw + 1];

    float m = -3.0e38f;
    for (int k = beg + lane; k < end; k += 32) m = fmaxf(m, g_se[k]);
#pragma unroll
    for (int o = 16; o; o >>= 1) m = fmaxf(m, __shfl_xor_sync(0xffffffffu, m, o));

    float s = 0.f;
    for (int k = beg + lane; k < end; k += 32) s += __expf(g_se[k] - m);
#pragma unroll
    for (int o = 16; o; o >>= 1) s += __shfl_xor_sync(0xffffffffu, s, o);
    float inv = 1.0f / s;

    float4 acc = make_float4(0.f, 0.f, 0.f, 0.f);
    for (int k0 = beg; k0 < end; k0 += 32) {
        int kk = k0 + lane;
        int   r   = 0;
        float att = 0.f;
        if (kk < end) {
            r   = g_srow[kk];
            att = __expf(g_se[kk] - m) * inv;
        }
        int cnt = min(32, end - k0);
        for (int j = 0; j < cnt; j++) {
            float aj = __shfl_sync(0xffffffffu, att, j);
            int   rj = __shfl_sync(0xffffffffu, r, j);
            float4 w = *(const float4*)(g_Wh + (size_t)rj * OUT_F + lane * 4);
            acc.x += aj * w.x;
            acc.y += aj * w.y;
            acc.z += aj * w.z;
            acc.w += aj * w.w;
        }
    }

    acc.x = (acc.x > 0.f) ? acc.x : (__expf(acc.x) - 1.f);
    acc.y = (acc.y > 0.f) ? acc.y : (__expf(acc.y) - 1.f);
    acc.z = (acc.z > 0.f) ? acc.z : (__expf(acc.z) - 1.f);
    acc.w = (acc.w > 0.f) ? acc.w : (__expf(acc.w) - 1.f);

    *(float4*)(out + (size_t)gw * OUT_F + lane * 4) = acc;
}

// ===================================================================
extern "C" void kernel_launch(void* const* d_in, const int* in_sizes, int n_in,
                              void* d_out, int out_size)
{
    (void)in_sizes; (void)n_in; (void)out_size;
    const float* h   = (const float*)d_in[0];
    const int*   adj = (const int*)d_in[1];
    const float* W   = (const float*)d_in[2];
    const float* a   = (const float*)d_in[3];
    float*       out = (float*)d_out;

    const int EB = (E_TOT + 255) / 256;
    const int WB = (N_NODES * 32 + 255) / 256;

    prep_kernel<<<SCAN_BLOCKS, 256>>>(W);
    gemm_mma_kernel<<<GEMM_CTAS, 256>>>(h, a);
    hist_kernel<<<EB, 256>>>(adj);
    scan_block_kernel<<<SCAN_BLOCKS, 256>>>();
    scan_top_kernel<<<1, 256>>>();
    scan_add_kernel<<<SCAN_BLOCKS, 256>>>();
    sort_scatter_kernel<<<EB, 256>>>(adj);
    aggregate_kernel<<<WB, 256>>>(out);
}